// round 11
// baseline (speedup 1.0000x reference)
#include <cuda_runtime.h>
#include <cuda_fp16.h>
#include <cstdint>

#define B_SZ 4
#define T_SZ 4096
#define DIM 512
#define E3 1536
#define HIST 128
#define M_TOT (B_SZ * T_SZ)   // 16384
#define QSCALE 0.04419417382415922f   // 1/sqrt(512)

// ---------------- device scratch (allocation-free rule) ----------------------
__device__ __align__(16) __half g_A[(size_t)M_TOT * DIM];
__device__ __align__(16) __half g_W[(size_t)E3 * DIM];
__device__ __align__(16) __half g_q[(size_t)M_TOT * DIM];
__device__ __align__(16) __half g_k[(size_t)M_TOT * DIM];
__device__ __align__(16) __half g_vt[(size_t)B_SZ * DIM * T_SZ];

// ---------------- helpers ----------------------------------------------------
__device__ __forceinline__ void mma16816(float* c, const uint32_t* a, uint32_t b0, uint32_t b1)
{
    asm volatile(
        "mma.sync.aligned.m16n8k16.row.col.f32.f16.f16.f32 "
        "{%0,%1,%2,%3}, {%4,%5,%6,%7}, {%8,%9}, {%0,%1,%2,%3};\n"
        : "+f"(c[0]), "+f"(c[1]), "+f"(c[2]), "+f"(c[3])
        : "r"(a[0]), "r"(a[1]), "r"(a[2]), "r"(a[3]), "r"(b0), "r"(b1));
}

__device__ __forceinline__ uint32_t sptr(const void* p)
{
    return (uint32_t)__cvta_generic_to_shared(p);
}

__device__ __forceinline__ void ldsm4(uint32_t* r, uint32_t addr)
{
    asm volatile("ldmatrix.sync.aligned.m8n8.x4.shared.b16 {%0,%1,%2,%3}, [%4];"
        : "=r"(r[0]), "=r"(r[1]), "=r"(r[2]), "=r"(r[3]) : "r"(addr));
}

__device__ __forceinline__ void ldsm2(uint32_t* r, uint32_t addr)
{
    asm volatile("ldmatrix.sync.aligned.m8n8.x2.shared.b16 {%0,%1}, [%2];"
        : "=r"(r[0]), "=r"(r[1]) : "r"(addr));
}

__device__ __forceinline__ void cpasync16(uint32_t dst, const void* src)
{
    asm volatile("cp.async.cg.shared.global [%0], [%1], 16;" :: "r"(dst), "l"(src));
}

__device__ __forceinline__ uint32_t packh(float a, float b)
{
    __half2 h = __floats2half2_rn(a, b);
    return *(uint32_t*)&h;
}

// ---------------- fp32 -> fp16 convert ---------------------------------------
__global__ __launch_bounds__(256) void cvt16(
    const float* __restrict__ src, __half* __restrict__ dst, int n4)
{
    int i = blockIdx.x * 256 + threadIdx.x;
    if (i >= n4) return;
    float4 v = ((const float4*)src)[i];
    uint2 u;
    u.x = packh(v.x, v.y);
    u.y = packh(v.z, v.w);
    ((uint2*)dst)[i] = u;
}

// ---------------- QKV GEMM: 128x256 block, warp 32x64, cp.async x2 -----------
#define GBM 128
#define GBN 256
#define GBK 64
#define GTHREADS 512
#define APITCH 72
#define MAT_A (GBM * APITCH)              // 9216 halves
#define MAT_B (GBN * APITCH)              // 18432 halves
#define STAGE_F (MAT_A + MAT_B)           // 27648 halves
#define GSMEM_BYTES (2 * STAGE_F * 2)     // 110592

__device__ __forceinline__ void gemm_load_stage(
    __half* stage, const __half* A, const __half* B, int k0, int tid)
{
    __half* sa = stage;
    __half* sb = stage + MAT_A;
#pragma unroll
    for (int it = 0; it < 2; it++) {
        const int idx = tid + it * GTHREADS;   // 0..1023
        const int r = idx >> 3;                // 0..127
        const int c = (idx & 7) * 8;
        cpasync16(sptr(sa + r * APITCH + c), A + (size_t)r * DIM + k0 + c);
    }
#pragma unroll
    for (int it = 0; it < 4; it++) {
        const int idx = tid + it * GTHREADS;   // 0..2047
        const int r = idx >> 3;                // 0..255
        const int c = (idx & 7) * 8;
        cpasync16(sptr(sb + r * APITCH + c), B + (size_t)r * DIM + k0 + c);
    }
}

__global__ __launch_bounds__(GTHREADS) void qkv_mma(const float* __restrict__ bias)
{
    extern __shared__ __align__(16) __half gsm[];

    const int tid  = threadIdx.x;
    const int warp = tid >> 5, lane = tid & 31;
    const int wm = (warp >> 2) * 32;     // 4 warps along M (128)
    const int wn = (warp & 3) * 64;      // 4 warps along N (256)
    const int g  = lane >> 2, tig = lane & 3;

    const int bm = blockIdx.y * GBM;
    const int bn = blockIdx.x * GBN;

    const __half* A = g_A + (size_t)bm * DIM;
    const __half* B = g_W + (size_t)bn * DIM;

    float acc[2][8][4] = {};

    const int arow = (lane & 15);
    const int acol = (lane >> 4) << 3;
    const int brow = ((lane >> 4) << 3) + (lane & 7);
    const int bcol = ((lane >> 3) & 1) << 3;

    gemm_load_stage(gsm, A, B, 0, tid);
    asm volatile("cp.async.commit_group;");

    const int NCH = DIM / GBK;   // 8
    for (int ch = 0; ch < NCH; ch++) {
        __half* stg = gsm + (ch & 1) * STAGE_F;
        if (ch + 1 < NCH) {
            gemm_load_stage(gsm + ((ch + 1) & 1) * STAGE_F, A, B, (ch + 1) * GBK, tid);
            asm volatile("cp.async.commit_group;");
            asm volatile("cp.async.wait_group 1;");
        } else {
            asm volatile("cp.async.wait_group 0;");
        }
        __syncthreads();

        __half* sA = stg;
        __half* sB = stg + MAT_A;

#pragma unroll
        for (int ks = 0; ks < GBK / 16; ks++) {
            const int k = ks * 16;
            uint32_t a[2][4];
#pragma unroll
            for (int mi = 0; mi < 2; mi++)
                ldsm4(a[mi], sptr(sA + (wm + mi * 16 + arow) * APITCH + k + acol));
#pragma unroll
            for (int np = 0; np < 4; np++) {
                uint32_t b[4];
                ldsm4(b, sptr(sB + (wn + np * 16 + brow) * APITCH + k + bcol));
#pragma unroll
                for (int mi = 0; mi < 2; mi++) {
                    mma16816(acc[mi][2 * np],     a[mi], b[0], b[1]);
                    mma16816(acc[mi][2 * np + 1], a[mi], b[2], b[3]);
                }
            }
        }
        __syncthreads();
    }

    // epilogue: bias, route to q (scaled) / k / v-transposed fp16 stores.
    // GBN=256 and sections are 512-wide & 256-aligned -> whole block in one sec.
    const int sec = bn >> 9;            // 0=q, 1=k, 2=v
#pragma unroll
    for (int mi = 0; mi < 2; mi++) {
#pragma unroll
        for (int ni = 0; ni < 8; ni++) {
            const int m0 = bm + wm + mi * 16 + g;
            const int cc = bn + wn + ni * 8 + tig * 2;
            const int lc = cc & 511;
            const float bb0 = bias[cc], bb1 = bias[cc + 1];
            float v00 = acc[mi][ni][0] + bb0, v01 = acc[mi][ni][1] + bb1;
            float v10 = acc[mi][ni][2] + bb0, v11 = acc[mi][ni][3] + bb1;
            if (sec == 0) { v00 *= QSCALE; v01 *= QSCALE; v10 *= QSCALE; v11 *= QSCALE; }
            const uint32_t p0 = packh(v00, v01);
            const uint32_t p1 = packh(v10, v11);
            if (sec == 0) {
                *(uint32_t*)&g_q[(size_t)m0 * DIM + lc]       = p0;
                *(uint32_t*)&g_q[(size_t)(m0 + 8) * DIM + lc] = p1;
            } else if (sec == 1) {
                *(uint32_t*)&g_k[(size_t)m0 * DIM + lc]       = p0;
                *(uint32_t*)&g_k[(size_t)(m0 + 8) * DIM + lc] = p1;
            } else {
                const int b = m0 >> 12, t = m0 & 4095;
                const size_t base = (size_t)b * DIM * T_SZ;
                g_vt[base + (size_t)lc * T_SZ + t]           = __float2half_rn(v00);
                g_vt[base + (size_t)(lc + 1) * T_SZ + t]     = __float2half_rn(v01);
                g_vt[base + (size_t)lc * T_SZ + t + 8]       = __float2half_rn(v10);
                g_vt[base + (size_t)(lc + 1) * T_SZ + t + 8] = __float2half_rn(v11);
            }
        }
    }
}

// ---------------- Banded attention: fp16, 2-stage pipelined ------------------
#define QT 32
#define NK 160
#define DC 64
#define KP 72
#define PP 168

// smem (bytes):
//  buf0: Qs0@0 (4608), Ks0@4608 (23040)     -> 27648
//  buf1: Qs1@27648,    Ks1@32256            -> 55296
//  phase B: Ps f32 @0 (21504)   [aliases buf0]
//  phase C: Vt0@0 (21504), Vt1@21504 (21504) [alias buf0/buf1]
//  Pw @55296 (10752)                         -> total 66048
#define AT_SMEM 66048

__global__ __launch_bounds__(256, 2) void attn_mma(float* __restrict__ out)
{
    extern __shared__ char sm[];
    __half* QsB[2] = {(__half*)sm,            (__half*)(sm + 27648)};
    __half* KsB[2] = {(__half*)(sm + 4608),   (__half*)(sm + 32256)};
    __half* VtB[2] = {(__half*)sm,            (__half*)(sm + 21504)};
    float*  Ps = (float*)sm;
    __half* Pw = (__half*)(sm + 55296);

    const int b   = blockIdx.y;
    const int i0  = blockIdx.x * QT;
    const int tid = threadIdx.x;
    const int warp = tid >> 5, lane = tid & 31;
    const int g = lane >> 2, tig = lane & 3;
    const int jbase = i0 - HIST;

    const int arow = lane & 15;
    const int acol = (lane >> 4) << 3;
    const int brow = ((lane >> 4) << 3) + (lane & 7);
    const int bcol = ((lane >> 3) & 1) << 3;
    const int l15  = lane & 15;
    const int b2row = l15 & 7;
    const int b2col = ((l15 >> 3) & 1) << 3;

    const int wm = (warp >> 2) * 16;       // 2 warp-groups along M (32)
    const int wn = (warp & 3) * 40;        // 4 warp-groups along N (160)

    // ---------------- phase A: S = Q K^T (pipelined over dc) -----------------
    float acc[5][4] = {};

    auto load_qk = [&](int dc, int sel) {
        const int d0 = dc * DC;
        __half* Qs = QsB[sel];
        __half* Ks = KsB[sel];
        {
            const int r = tid >> 3, c8 = (tid & 7) * 8;
            const size_t off = (size_t)(b * T_SZ + i0 + r) * DIM + d0 + c8;
            cpasync16(sptr(&Qs[r * KP + c8]), g_q + off);
        }
#pragma unroll
        for (int it = 0; it < 5; it++) {
            const int idx = tid + it * 256;
            const int r = idx >> 3, c8 = (idx & 7) * 8;
            const int j = jbase + r;
            const int jc = j < 0 ? 0 : j;
            const size_t off = (size_t)(b * T_SZ + jc) * DIM + d0 + c8;
            cpasync16(sptr(&Ks[r * KP + c8]), g_k + off);
        }
        asm volatile("cp.async.commit_group;");
    };

    load_qk(0, 0);

    for (int dc = 0; dc < DIM / DC; dc++) {
        const int cur = dc & 1;
        if (dc + 1 < DIM / DC) {
            __syncthreads();                 // done reading buf[cur^1] (iter dc-1)
            load_qk(dc + 1, cur ^ 1);
            asm volatile("cp.async.wait_group 1;");   // dc ready, dc+1 in flight
        } else {
            asm volatile("cp.async.wait_group 0;");
        }
        __syncthreads();

        __half* Qs = QsB[cur];
        __half* Ks = KsB[cur];
#pragma unroll
        for (int ks = 0; ks < DC / 16; ks++) {
            const int k = ks * 16;
            uint32_t a[4];
            ldsm4(a, sptr(&Qs[(wm + arow) * KP + k + acol]));
            uint32_t bb[10];
            ldsm4(bb,     sptr(&Ks[(wn +      brow) * KP + k + bcol]));
            ldsm4(bb + 4, sptr(&Ks[(wn + 16 + brow) * KP + k + bcol]));
            ldsm2(bb + 8, sptr(&Ks[(wn + 32 + b2row) * KP + k + b2col]));
#pragma unroll
            for (int ni = 0; ni < 5; ni++)
                mma16816(acc[ni], a, bb[2 * ni], bb[2 * ni + 1]);
        }
    }
    __syncthreads();

    // masked store of S to Ps
#pragma unroll
    for (int ni = 0; ni < 5; ni++) {
        const int m0 = wm + g;
        const int n0 = wn + ni * 8 + tig * 2;
#pragma unroll
        for (int e = 0; e < 4; e++) {
            const int m = m0 + (e >> 1) * 8;
            const int n = n0 + (e & 1);
            const bool valid = (n >= m) && (n <= m + HIST) && (jbase + n >= 0);
            Ps[m * PP + n] = valid ? acc[ni][e] : -1e30f;
        }
    }
    __syncthreads();

    // ---------------- phase B: softmax + fp16 P ------------------------------
#pragma unroll
    for (int rr = 0; rr < 4; rr++) {
        const int q = warp * 4 + rr;
        float v[5];
        float mx = -1e30f;
#pragma unroll
        for (int s = 0; s < 5; s++) {
            v[s] = Ps[q * PP + lane + 32 * s];
            mx = fmaxf(mx, v[s]);
        }
#pragma unroll
        for (int off = 16; off; off >>= 1)
            mx = fmaxf(mx, __shfl_xor_sync(0xFFFFFFFFu, mx, off));
        float sum = 0.f;
#pragma unroll
        for (int s = 0; s < 5; s++) {
            v[s] = __expf(v[s] - mx);
            sum += v[s];
        }
#pragma unroll
        for (int off = 16; off; off >>= 1)
            sum += __shfl_xor_sync(0xFFFFFFFFu, sum, off);
        const float inv = 1.f / sum;
#pragma unroll
        for (int s = 0; s < 5; s++)
            Pw[q * PP + lane + 32 * s] = __float2half_rn(v[s] * inv);
    }
    __syncthreads();   // Ps reads done before Vt loads overwrite region

    // ---------------- phase C: O = P V (pipelined over dc) -------------------
    const int wn2 = (warp & 3) * 16;       // 4 warp-groups along D (64)
    const size_t vbase = (size_t)b * DIM * T_SZ;

    auto load_v = [&](int dc, int sel) {
        const int d0 = dc * DC;
        __half* Vt = VtB[sel];
#pragma unroll
        for (int it = 0; it < 5; it++) {
            const int idx = tid + it * 256;
            const int r = idx / 20;
            const int c8 = (idx % 20) * 8;
            int j = jbase + c8;
            if (j < 0) j = 0;
            const size_t off = vbase + (size_t)(d0 + r) * T_SZ + j;
            cpasync16(sptr(&Vt[r * PP + c8]), g_vt + off);
        }
        asm volatile("cp.async.commit_group;");
    };

    load_v(0, 0);

    for (int dc = 0; dc < DIM / DC; dc++) {
        const int cur = dc & 1;
        if (dc + 1 < DIM / DC) {
            __syncthreads();
            load_v(dc + 1, cur ^ 1);
            asm volatile("cp.async.wait_group 1;");
        } else {
            asm volatile("cp.async.wait_group 0;");
        }
        __syncthreads();

        __half* Vt = VtB[cur];
        const int d0 = dc * DC;

        float oacc[2][4] = {};
#pragma unroll
        for (int ks = 0; ks < NK / 16; ks++) {
            const int k = ks * 16;
            uint32_t pw[4], vv[4];
            ldsm4(pw, sptr(&Pw[(wm + arow) * PP + k + acol]));
            ldsm4(vv, sptr(&Vt[(wn2 + brow) * PP + k + bcol]));
            mma16816(oacc[0], pw, vv[0], vv[1]);
            mma16816(oacc[1], pw, vv[2], vv[3]);
        }

#pragma unroll
        for (int ni = 0; ni < 2; ni++) {
            const int m0 = wm + g;
            const int col = d0 + wn2 + ni * 8 + tig * 2;
            const size_t row = (size_t)b * T_SZ + i0 + m0;
            float2 v0 = {oacc[ni][0], oacc[ni][1]};
            float2 v1 = {oacc[ni][2], oacc[ni][3]};
            *(float2*)&out[row * DIM + col]       = v0;
            *(float2*)&out[(row + 8) * DIM + col] = v1;
        }
    }
}

// ---------------- launch -----------------------------------------------------
extern "C" void kernel_launch(void* const* d_in, const int* in_sizes, int n_in,
                              void* d_out, int out_size)
{
    const float* x    = (const float*)d_in[0];
    const float* Wqkv = (const float*)d_in[1];
    const float* bqkv = (const float*)d_in[2];
    float* out = (float*)d_out;

    cudaFuncSetAttribute(attn_mma,
                         cudaFuncAttributeMaxDynamicSharedMemorySize, AT_SMEM);
    cudaFuncSetAttribute(qkv_mma,
                         cudaFuncAttributeMaxDynamicSharedMemorySize, GSMEM_BYTES);

    __half *pa, *pw;
    cudaGetSymbolAddress((void**)&pa, g_A);
    cudaGetSymbolAddress((void**)&pw, g_W);

    {
        int n4 = (M_TOT * DIM) / 4;
        cvt16<<<(n4 + 255) / 256, 256>>>(x, pa, n4);
    }
    {
        int n4 = (E3 * DIM) / 4;
        cvt16<<<(n4 + 255) / 256, 256>>>(Wqkv, pw, n4);
    }

    dim3 ggrid(E3 / GBN, M_TOT / GBM);       // (6, 128)
    qkv_mma<<<ggrid, GTHREADS, GSMEM_BYTES>>>(bqkv);

    dim3 agrid(T_SZ / QT, B_SZ);             // (128, 4)
    attn_mma<<<agrid, 256, AT_SMEM>>>(out);
}

// round 13
// speedup vs baseline: 1.0890x; 1.0890x over previous
#include <cuda_runtime.h>
#include <cuda_fp16.h>
#include <cstdint>

#define B_SZ 4
#define T_SZ 4096
#define DIM 512
#define E3 1536
#define HIST 128
#define M_TOT (B_SZ * T_SZ)   // 16384
#define QSCALE 0.04419417382415922f   // 1/sqrt(512)

// ---------------- device scratch (allocation-free rule) ----------------------
__device__ __align__(16) __half g_A[(size_t)M_TOT * DIM];
__device__ __align__(16) __half g_W[(size_t)E3 * DIM];
__device__ __align__(16) __half g_q[(size_t)M_TOT * DIM];
__device__ __align__(16) __half g_k[(size_t)M_TOT * DIM];
__device__ __align__(16) __half g_vt[(size_t)B_SZ * DIM * T_SZ];

// ---------------- helpers ----------------------------------------------------
__device__ __forceinline__ void mma16816(float* c, const uint32_t* a, uint32_t b0, uint32_t b1)
{
    asm volatile(
        "mma.sync.aligned.m16n8k16.row.col.f32.f16.f16.f32 "
        "{%0,%1,%2,%3}, {%4,%5,%6,%7}, {%8,%9}, {%0,%1,%2,%3};\n"
        : "+f"(c[0]), "+f"(c[1]), "+f"(c[2]), "+f"(c[3])
        : "r"(a[0]), "r"(a[1]), "r"(a[2]), "r"(a[3]), "r"(b0), "r"(b1));
}

__device__ __forceinline__ uint32_t sptr(const void* p)
{
    return (uint32_t)__cvta_generic_to_shared(p);
}

__device__ __forceinline__ void ldsm4(uint32_t* r, uint32_t addr)
{
    asm volatile("ldmatrix.sync.aligned.m8n8.x4.shared.b16 {%0,%1,%2,%3}, [%4];"
        : "=r"(r[0]), "=r"(r[1]), "=r"(r[2]), "=r"(r[3]) : "r"(addr));
}

__device__ __forceinline__ void ldsm2(uint32_t* r, uint32_t addr)
{
    asm volatile("ldmatrix.sync.aligned.m8n8.x2.shared.b16 {%0,%1}, [%2];"
        : "=r"(r[0]), "=r"(r[1]) : "r"(addr));
}

__device__ __forceinline__ void cpasync16(uint32_t dst, const void* src)
{
    asm volatile("cp.async.cg.shared.global [%0], [%1], 16;" :: "r"(dst), "l"(src));
}

__device__ __forceinline__ uint32_t packh(float a, float b)
{
    __half2 h = __floats2half2_rn(a, b);
    return *(uint32_t*)&h;
}

// ---------------- fp32 -> fp16 convert (x and W fused) -----------------------
#define NX4 ((M_TOT * DIM) / 4)   // 2097152
#define NW4 ((E3 * DIM) / 4)      // 196608

__global__ __launch_bounds__(256) void cvt16_both(
    const float* __restrict__ x, const float* __restrict__ w,
    __half* __restrict__ dA, __half* __restrict__ dW)
{
    int i = blockIdx.x * 256 + threadIdx.x;
    const float* src;
    __half* dst;
    int idx;
    if (i < NX4) { src = x; dst = dA; idx = i; }
    else if (i < NX4 + NW4) { src = w; dst = dW; idx = i - NX4; }
    else return;
    float4 v = ((const float4*)src)[idx];
    uint2 u;
    u.x = packh(v.x, v.y);
    u.y = packh(v.z, v.w);
    ((uint2*)dst)[idx] = u;
}

// ---------------- QKV GEMM: R10 config (GBN=128), cp.async x2, ldmatrix ------
#define GBM 128
#define GBN 128
#define GBK 64
#define GTHREADS 512
#define APITCH 72
#define MAT_F (GBM * APITCH)              // 9216 halves per matrix
#define STAGE_F (2 * MAT_F)               // A, B
#define GSMEM_BYTES (2 * STAGE_F * 2)     // 73728

__device__ __forceinline__ void gemm_load_stage(
    __half* stage, const __half* A, const __half* B, int k0, int tid)
{
    const __half* srcs[2] = {A, B};
#pragma unroll
    for (int m = 0; m < 2; m++) {
        __half* mb = stage + m * MAT_F;
        const __half* gb = srcs[m];
#pragma unroll
        for (int it = 0; it < 2; it++) {
            const int idx = tid + it * GTHREADS;   // 0..1023
            const int r = idx >> 3;
            const int c = (idx & 7) * 8;
            cpasync16(sptr(mb + r * APITCH + c), gb + (size_t)r * DIM + k0 + c);
        }
    }
}

__global__ __launch_bounds__(GTHREADS) void qkv_mma(const float* __restrict__ bias)
{
    extern __shared__ __align__(16) __half gsm[];

    const int tid  = threadIdx.x;
    const int warp = tid >> 5, lane = tid & 31;
    const int wm = (warp >> 2) * 32;
    const int wn = (warp & 3) * 32;
    const int g  = lane >> 2, tig = lane & 3;

    const int bm = blockIdx.y * GBM;
    const int bn = blockIdx.x * GBN;

    const __half* A = g_A + (size_t)bm * DIM;
    const __half* B = g_W + (size_t)bn * DIM;

    float acc[2][4][4] = {};

    const int arow = (lane & 15);
    const int acol = (lane >> 4) << 3;
    const int brow = ((lane >> 4) << 3) + (lane & 7);
    const int bcol = ((lane >> 3) & 1) << 3;

    gemm_load_stage(gsm, A, B, 0, tid);
    asm volatile("cp.async.commit_group;");

    const int NCH = DIM / GBK;   // 8
    for (int ch = 0; ch < NCH; ch++) {
        __half* stg = gsm + (ch & 1) * STAGE_F;
        if (ch + 1 < NCH) {
            gemm_load_stage(gsm + ((ch + 1) & 1) * STAGE_F, A, B, (ch + 1) * GBK, tid);
            asm volatile("cp.async.commit_group;");
            asm volatile("cp.async.wait_group 1;");
        } else {
            asm volatile("cp.async.wait_group 0;");
        }
        __syncthreads();

        __half* sA = stg;
        __half* sB = stg + MAT_F;

#pragma unroll
        for (int ks = 0; ks < GBK / 16; ks++) {
            const int k = ks * 16;
            uint32_t a[2][4];
#pragma unroll
            for (int mi = 0; mi < 2; mi++)
                ldsm4(a[mi], sptr(sA + (wm + mi * 16 + arow) * APITCH + k + acol));
#pragma unroll
            for (int np = 0; np < 2; np++) {
                uint32_t b[4];
                ldsm4(b, sptr(sB + (wn + np * 16 + brow) * APITCH + k + bcol));
#pragma unroll
                for (int mi = 0; mi < 2; mi++) {
                    mma16816(acc[mi][2 * np],     a[mi], b[0], b[1]);
                    mma16816(acc[mi][2 * np + 1], a[mi], b[2], b[3]);
                }
            }
        }
        __syncthreads();
    }

    // epilogue: bias, route to q (scaled) / k / v-transposed fp16 stores
    const int sec = bn >> 9;            // 0=q, 1=k, 2=v
#pragma unroll
    for (int mi = 0; mi < 2; mi++) {
#pragma unroll
        for (int ni = 0; ni < 4; ni++) {
            const int m0 = bm + wm + mi * 16 + g;
            const int cc = bn + wn + ni * 8 + tig * 2;
            const int lc = cc & 511;
            const float bb0 = bias[cc], bb1 = bias[cc + 1];
            float v00 = acc[mi][ni][0] + bb0, v01 = acc[mi][ni][1] + bb1;
            float v10 = acc[mi][ni][2] + bb0, v11 = acc[mi][ni][3] + bb1;
            if (sec == 0) { v00 *= QSCALE; v01 *= QSCALE; v10 *= QSCALE; v11 *= QSCALE; }
            const uint32_t p0 = packh(v00, v01);
            const uint32_t p1 = packh(v10, v11);
            if (sec == 0) {
                *(uint32_t*)&g_q[(size_t)m0 * DIM + lc]       = p0;
                *(uint32_t*)&g_q[(size_t)(m0 + 8) * DIM + lc] = p1;
            } else if (sec == 1) {
                *(uint32_t*)&g_k[(size_t)m0 * DIM + lc]       = p0;
                *(uint32_t*)&g_k[(size_t)(m0 + 8) * DIM + lc] = p1;
            } else {
                const int b = m0 >> 12, t = m0 & 4095;
                const size_t base = (size_t)b * DIM * T_SZ;
                g_vt[base + (size_t)lc * T_SZ + t]           = __float2half_rn(v00);
                g_vt[base + (size_t)(lc + 1) * T_SZ + t]     = __float2half_rn(v01);
                g_vt[base + (size_t)lc * T_SZ + t + 8]       = __float2half_rn(v10);
                g_vt[base + (size_t)(lc + 1) * T_SZ + t + 8] = __float2half_rn(v11);
            }
        }
    }
}

// ---------------- Banded attention: fp16, 2-stage pipelined (R11) ------------
#define QT 32
#define NK 160
#define DC 64
#define KP 72
#define PP 168

#define AT_SMEM 66048

__global__ __launch_bounds__(256, 2) void attn_mma(float* __restrict__ out)
{
    extern __shared__ char sm[];
    __half* QsB[2] = {(__half*)sm,            (__half*)(sm + 27648)};
    __half* KsB[2] = {(__half*)(sm + 4608),   (__half*)(sm + 32256)};
    __half* VtB[2] = {(__half*)sm,            (__half*)(sm + 21504)};
    float*  Ps = (float*)sm;
    __half* Pw = (__half*)(sm + 55296);

    const int b   = blockIdx.y;
    const int i0  = blockIdx.x * QT;
    const int tid = threadIdx.x;
    const int warp = tid >> 5, lane = tid & 31;
    const int g = lane >> 2, tig = lane & 3;
    const int jbase = i0 - HIST;

    const int arow = lane & 15;
    const int acol = (lane >> 4) << 3;
    const int brow = ((lane >> 4) << 3) + (lane & 7);
    const int bcol = ((lane >> 3) & 1) << 3;
    const int l15  = lane & 15;
    const int b2row = l15 & 7;
    const int b2col = ((l15 >> 3) & 1) << 3;

    const int wm = (warp >> 2) * 16;       // 2 warp-groups along M (32)
    const int wn = (warp & 3) * 40;        // 4 warp-groups along N (160)

    // ---------------- phase A: S = Q K^T (pipelined over dc) -----------------
    float acc[5][4] = {};

    auto load_qk = [&](int dc, int sel) {
        const int d0 = dc * DC;
        __half* Qs = QsB[sel];
        __half* Ks = KsB[sel];
        {
            const int r = tid >> 3, c8 = (tid & 7) * 8;
            const size_t off = (size_t)(b * T_SZ + i0 + r) * DIM + d0 + c8;
            cpasync16(sptr(&Qs[r * KP + c8]), g_q + off);
        }
#pragma unroll
        for (int it = 0; it < 5; it++) {
            const int idx = tid + it * 256;
            const int r = idx >> 3, c8 = (idx & 7) * 8;
            const int j = jbase + r;
            const int jc = j < 0 ? 0 : j;
            const size_t off = (size_t)(b * T_SZ + jc) * DIM + d0 + c8;
            cpasync16(sptr(&Ks[r * KP + c8]), g_k + off);
        }
        asm volatile("cp.async.commit_group;");
    };

    load_qk(0, 0);

    for (int dc = 0; dc < DIM / DC; dc++) {
        const int cur = dc & 1;
        if (dc + 1 < DIM / DC) {
            __syncthreads();                 // done reading buf[cur^1] (iter dc-1)
            load_qk(dc + 1, cur ^ 1);
            asm volatile("cp.async.wait_group 1;");   // dc ready, dc+1 in flight
        } else {
            asm volatile("cp.async.wait_group 0;");
        }
        __syncthreads();

        __half* Qs = QsB[cur];
        __half* Ks = KsB[cur];
#pragma unroll
        for (int ks = 0; ks < DC / 16; ks++) {
            const int k = ks * 16;
            uint32_t a[4];
            ldsm4(a, sptr(&Qs[(wm + arow) * KP + k + acol]));
            uint32_t bb[10];
            ldsm4(bb,     sptr(&Ks[(wn +      brow) * KP + k + bcol]));
            ldsm4(bb + 4, sptr(&Ks[(wn + 16 + brow) * KP + k + bcol]));
            ldsm2(bb + 8, sptr(&Ks[(wn + 32 + b2row) * KP + k + b2col]));
#pragma unroll
            for (int ni = 0; ni < 5; ni++)
                mma16816(acc[ni], a, bb[2 * ni], bb[2 * ni + 1]);
        }
    }
    __syncthreads();

    // masked store of S to Ps
#pragma unroll
    for (int ni = 0; ni < 5; ni++) {
        const int m0 = wm + g;
        const int n0 = wn + ni * 8 + tig * 2;
#pragma unroll
        for (int e = 0; e < 4; e++) {
            const int m = m0 + (e >> 1) * 8;
            const int n = n0 + (e & 1);
            const bool valid = (n >= m) && (n <= m + HIST) && (jbase + n >= 0);
            Ps[m * PP + n] = valid ? acc[ni][e] : -1e30f;
        }
    }
    __syncthreads();

    // ---------------- phase B: softmax + fp16 P ------------------------------
#pragma unroll
    for (int rr = 0; rr < 4; rr++) {
        const int q = warp * 4 + rr;
        float v[5];
        float mx = -1e30f;
#pragma unroll
        for (int s = 0; s < 5; s++) {
            v[s] = Ps[q * PP + lane + 32 * s];
            mx = fmaxf(mx, v[s]);
        }
#pragma unroll
        for (int off = 16; off; off >>= 1)
            mx = fmaxf(mx, __shfl_xor_sync(0xFFFFFFFFu, mx, off));
        float sum = 0.f;
#pragma unroll
        for (int s = 0; s < 5; s++) {
            v[s] = __expf(v[s] - mx);
            sum += v[s];
        }
#pragma unroll
        for (int off = 16; off; off >>= 1)
            sum += __shfl_xor_sync(0xFFFFFFFFu, sum, off);
        const float inv = 1.f / sum;
#pragma unroll
        for (int s = 0; s < 5; s++)
            Pw[q * PP + lane + 32 * s] = __float2half_rn(v[s] * inv);
    }
    __syncthreads();   // Ps reads done before Vt loads overwrite region

    // ---------------- phase C: O = P V (pipelined over dc) -------------------
    const int wn2 = (warp & 3) * 16;       // 4 warp-groups along D (64)
    const size_t vbase = (size_t)b * DIM * T_SZ;

    auto load_v = [&](int dc, int sel) {
        const int d0 = dc * DC;
        __half* Vt = VtB[sel];
#pragma unroll
        for (int it = 0; it < 5; it++) {
            const int idx = tid + it * 256;
            const int r = idx / 20;
            const int c8 = (idx % 20) * 8;
            int j = jbase + c8;
            if (j < 0) j = 0;
            const size_t off = vbase + (size_t)(d0 + r) * T_SZ + j;
            cpasync16(sptr(&Vt[r * PP + c8]), g_vt + off);
        }
        asm volatile("cp.async.commit_group;");
    };

    load_v(0, 0);

    for (int dc = 0; dc < DIM / DC; dc++) {
        const int cur = dc & 1;
        if (dc + 1 < DIM / DC) {
            __syncthreads();
            load_v(dc + 1, cur ^ 1);
            asm volatile("cp.async.wait_group 1;");
        } else {
            asm volatile("cp.async.wait_group 0;");
        }
        __syncthreads();

        __half* Vt = VtB[cur];
        const int d0 = dc * DC;

        float oacc[2][4] = {};
#pragma unroll
        for (int ks = 0; ks < NK / 16; ks++) {
            const int k = ks * 16;
            uint32_t pw[4], vv[4];
            ldsm4(pw, sptr(&Pw[(wm + arow) * PP + k + acol]));
            ldsm4(vv, sptr(&Vt[(wn2 + brow) * PP + k + bcol]));
            mma16816(oacc[0], pw, vv[0], vv[1]);
            mma16816(oacc[1], pw, vv[2], vv[3]);
        }

#pragma unroll
        for (int ni = 0; ni < 2; ni++) {
            const int m0 = wm + g;
            const int col = d0 + wn2 + ni * 8 + tig * 2;
            const size_t row = (size_t)b * T_SZ + i0 + m0;
            float2 v0 = {oacc[ni][0], oacc[ni][1]};
            float2 v1 = {oacc[ni][2], oacc[ni][3]};
            *(float2*)&out[row * DIM + col]       = v0;
            *(float2*)&out[(row + 8) * DIM + col] = v1;
        }
    }
}

// ---------------- launch -----------------------------------------------------
extern "C" void kernel_launch(void* const* d_in, const int* in_sizes, int n_in,
                              void* d_out, int out_size)
{
    const float* x    = (const float*)d_in[0];
    const float* Wqkv = (const float*)d_in[1];
    const float* bqkv = (const float*)d_in[2];
    float* out = (float*)d_out;

    cudaFuncSetAttribute(attn_mma,
                         cudaFuncAttributeMaxDynamicSharedMemorySize, AT_SMEM);
    cudaFuncSetAttribute(qkv_mma,
                         cudaFuncAttributeMaxDynamicSharedMemorySize, GSMEM_BYTES);

    __half *pa, *pw;
    cudaGetSymbolAddress((void**)&pa, g_A);
    cudaGetSymbolAddress((void**)&pw, g_W);

    {
        int n4 = NX4 + NW4;
        cvt16_both<<<(n4 + 255) / 256, 256>>>(x, Wqkv, pa, pw);
    }

    dim3 ggrid(E3 / GBN, M_TOT / GBM);       // (12, 128)
    qkv_mma<<<ggrid, GTHREADS, GSMEM_BYTES>>>(bqkv);

    dim3 agrid(T_SZ / QT, B_SZ);             // (128, 4)
    attn_mma<<<agrid, 256, AT_SMEM>>>(out);
}

// round 14
// speedup vs baseline: 1.1024x; 1.0123x over previous
#include <cuda_runtime.h>
#include <cuda_fp16.h>
#include <cstdint>

#define B_SZ 4
#define T_SZ 4096
#define DIM 512
#define E3 1536
#define HIST 128
#define M_TOT (B_SZ * T_SZ)   // 16384
#define QSCALE 0.04419417382415922f   // 1/sqrt(512)

// ---------------- device scratch (allocation-free rule) ----------------------
__device__ __align__(16) __half g_A[(size_t)M_TOT * DIM];
__device__ __align__(16) __half g_W[(size_t)E3 * DIM];
__device__ __align__(16) __half g_q[(size_t)M_TOT * DIM];
__device__ __align__(16) __half g_k[(size_t)M_TOT * DIM];
__device__ __align__(16) __half g_vt[(size_t)B_SZ * DIM * T_SZ];

// ---------------- helpers ----------------------------------------------------
__device__ __forceinline__ void mma16816(float* c, const uint32_t* a, uint32_t b0, uint32_t b1)
{
    asm volatile(
        "mma.sync.aligned.m16n8k16.row.col.f32.f16.f16.f32 "
        "{%0,%1,%2,%3}, {%4,%5,%6,%7}, {%8,%9}, {%0,%1,%2,%3};\n"
        : "+f"(c[0]), "+f"(c[1]), "+f"(c[2]), "+f"(c[3])
        : "r"(a[0]), "r"(a[1]), "r"(a[2]), "r"(a[3]), "r"(b0), "r"(b1));
}

__device__ __forceinline__ uint32_t sptr(const void* p)
{
    return (uint32_t)__cvta_generic_to_shared(p);
}

__device__ __forceinline__ void ldsm4(uint32_t* r, uint32_t addr)
{
    asm volatile("ldmatrix.sync.aligned.m8n8.x4.shared.b16 {%0,%1,%2,%3}, [%4];"
        : "=r"(r[0]), "=r"(r[1]), "=r"(r[2]), "=r"(r[3]) : "r"(addr));
}

__device__ __forceinline__ void cpasync16(uint32_t dst, const void* src)
{
    asm volatile("cp.async.cg.shared.global [%0], [%1], 16;" :: "r"(dst), "l"(src));
}

__device__ __forceinline__ uint32_t packh(float a, float b)
{
    __half2 h = __floats2half2_rn(a, b);
    return *(uint32_t*)&h;
}

// ---------------- fp32 -> fp16 convert (x and W fused) -----------------------
#define NX4 ((M_TOT * DIM) / 4)   // 2097152
#define NW4 ((E3 * DIM) / 4)      // 196608

__global__ __launch_bounds__(256) void cvt16_both(
    const float* __restrict__ x, const float* __restrict__ w,
    __half* __restrict__ dA, __half* __restrict__ dW)
{
    int i = blockIdx.x * 256 + threadIdx.x;
    const float* src;
    __half* dst;
    int idx;
    if (i < NX4) { src = x; dst = dA; idx = i; }
    else if (i < NX4 + NW4) { src = w; dst = dW; idx = i - NX4; }
    else return;
    float4 v = ((const float4*)src)[idx];
    uint2 u;
    u.x = packh(v.x, v.y);
    u.y = packh(v.z, v.w);
    ((uint2*)dst)[idx] = u;
}

// ---------------- QKV GEMM: 3-stage cp.async pipeline, 1 barrier/chunk -------
#define GBM 128
#define GBN 128
#define GBK 64
#define GTHREADS 512
#define APITCH 72
#define MAT_F (GBM * APITCH)              // 9216 halves per matrix
#define STAGE_F (2 * MAT_F)               // A, B
#define GSMEM_BYTES (3 * STAGE_F * 2)     // 110592

__device__ __forceinline__ void gemm_load_stage(
    __half* stage, const __half* A, const __half* B, int k0, int tid)
{
    const __half* srcs[2] = {A, B};
#pragma unroll
    for (int m = 0; m < 2; m++) {
        __half* mb = stage + m * MAT_F;
        const __half* gb = srcs[m];
#pragma unroll
        for (int it = 0; it < 2; it++) {
            const int idx = tid + it * GTHREADS;   // 0..1023
            const int r = idx >> 3;
            const int c = (idx & 7) * 8;
            cpasync16(sptr(mb + r * APITCH + c), gb + (size_t)r * DIM + k0 + c);
        }
    }
}

__global__ __launch_bounds__(GTHREADS) void qkv_mma(const float* __restrict__ bias)
{
    extern __shared__ __align__(16) __half gsm[];

    const int tid  = threadIdx.x;
    const int warp = tid >> 5, lane = tid & 31;
    const int wm = (warp >> 2) * 32;
    const int wn = (warp & 3) * 32;
    const int g  = lane >> 2, tig = lane & 3;

    const int bm = blockIdx.y * GBM;
    const int bn = blockIdx.x * GBN;

    const __half* A = g_A + (size_t)bm * DIM;
    const __half* B = g_W + (size_t)bn * DIM;

    float acc[2][4][4] = {};

    const int arow = (lane & 15);
    const int acol = (lane >> 4) << 3;
    const int brow = ((lane >> 4) << 3) + (lane & 7);
    const int bcol = ((lane >> 3) & 1) << 3;

    gemm_load_stage(gsm, A, B, 0, tid);
    asm volatile("cp.async.commit_group;");
    gemm_load_stage(gsm + STAGE_F, A, B, GBK, tid);
    asm volatile("cp.async.commit_group;");

    const int NCH = DIM / GBK;   // 8
    for (int ch = 0; ch < NCH; ch++) {
        if (ch + 1 < NCH) {
            asm volatile("cp.async.wait_group 1;");
        } else {
            asm volatile("cp.async.wait_group 0;");
        }
        __syncthreads();
        if (ch + 2 < NCH) {
            gemm_load_stage(gsm + ((ch + 2) % 3) * STAGE_F, A, B, (ch + 2) * GBK, tid);
            asm volatile("cp.async.commit_group;");
        }

        __half* stg = gsm + (ch % 3) * STAGE_F;
        __half* sA = stg;
        __half* sB = stg + MAT_F;

#pragma unroll
        for (int ks = 0; ks < GBK / 16; ks++) {
            const int k = ks * 16;
            uint32_t a[2][4];
#pragma unroll
            for (int mi = 0; mi < 2; mi++)
                ldsm4(a[mi], sptr(sA + (wm + mi * 16 + arow) * APITCH + k + acol));
#pragma unroll
            for (int np = 0; np < 2; np++) {
                uint32_t b[4];
                ldsm4(b, sptr(sB + (wn + np * 16 + brow) * APITCH + k + bcol));
#pragma unroll
                for (int mi = 0; mi < 2; mi++) {
                    mma16816(acc[mi][2 * np],     a[mi], b[0], b[1]);
                    mma16816(acc[mi][2 * np + 1], a[mi], b[2], b[3]);
                }
            }
        }
    }

    // epilogue: bias, route to q (scaled) / k / v-transposed fp16 stores
    const int sec = bn >> 9;            // 0=q, 1=k, 2=v
#pragma unroll
    for (int mi = 0; mi < 2; mi++) {
#pragma unroll
        for (int ni = 0; ni < 4; ni++) {
            const int m0 = bm + wm + mi * 16 + g;
            const int cc = bn + wn + ni * 8 + tig * 2;
            const int lc = cc & 511;
            const float bb0 = bias[cc], bb1 = bias[cc + 1];
            float v00 = acc[mi][ni][0] + bb0, v01 = acc[mi][ni][1] + bb1;
            float v10 = acc[mi][ni][2] + bb0, v11 = acc[mi][ni][3] + bb1;
            if (sec == 0) { v00 *= QSCALE; v01 *= QSCALE; v10 *= QSCALE; v11 *= QSCALE; }
            const uint32_t p0 = packh(v00, v01);
            const uint32_t p1 = packh(v10, v11);
            if (sec == 0) {
                *(uint32_t*)&g_q[(size_t)m0 * DIM + lc]       = p0;
                *(uint32_t*)&g_q[(size_t)(m0 + 8) * DIM + lc] = p1;
            } else if (sec == 1) {
                *(uint32_t*)&g_k[(size_t)m0 * DIM + lc]       = p0;
                *(uint32_t*)&g_k[(size_t)(m0 + 8) * DIM + lc] = p1;
            } else {
                const int b = m0 >> 12, t = m0 & 4095;
                const size_t base = (size_t)b * DIM * T_SZ;
                g_vt[base + (size_t)lc * T_SZ + t]           = __float2half_rn(v00);
                g_vt[base + (size_t)(lc + 1) * T_SZ + t]     = __float2half_rn(v01);
                g_vt[base + (size_t)lc * T_SZ + t + 8]       = __float2half_rn(v10);
                g_vt[base + (size_t)(lc + 1) * T_SZ + t + 8] = __float2half_rn(v11);
            }
        }
    }
}

// ---------------- Banded attention: QT=64, fp16, 2-stage pipelined -----------
#define QT 64
#define NK 192
#define DC 64
#define KP 72
#define PP 200

// smem (bytes):
//  buf0: Qs0@0 (9216), Ks0@9216 (27648)    -> 36864
//  buf1: Qs1@36864,    Ks1@46080           -> 73728
//  phase B: Ps f32 @0 (64*200*4 = 51200)   [aliases bufs]
//  phase C: Vt0@0 (25600), Vt1@25600       [aliases bufs]
//  Pw @73728 (64*200*2 = 25600)            -> total 99328
#define AT_SMEM 99328

__global__ __launch_bounds__(256, 2) void attn_mma(float* __restrict__ out)
{
    extern __shared__ char sm[];
    __half* QsB[2] = {(__half*)sm,            (__half*)(sm + 36864)};
    __half* KsB[2] = {(__half*)(sm + 9216),   (__half*)(sm + 46080)};
    __half* VtB[2] = {(__half*)sm,            (__half*)(sm + 25600)};
    float*  Ps = (float*)sm;
    __half* Pw = (__half*)(sm + 73728);

    const int b   = blockIdx.y;
    const int i0  = blockIdx.x * QT;
    const int tid = threadIdx.x;
    const int warp = tid >> 5, lane = tid & 31;
    const int g = lane >> 2, tig = lane & 3;
    const int jbase = i0 - HIST;

    const int arow = lane & 15;
    const int acol = (lane >> 4) << 3;
    const int brow = ((lane >> 4) << 3) + (lane & 7);
    const int bcol = ((lane >> 3) & 1) << 3;

    const int wm = (warp >> 2) * 32;       // 2 warp-groups along M (64)
    const int wn = (warp & 3) * 48;        // 4 warp-groups along N (192)

    // ---------------- phase A: S = Q K^T (pipelined over dc) -----------------
    float acc[2][6][4] = {};

    auto load_qk = [&](int dc, int sel) {
        const int d0 = dc * DC;
        __half* Qs = QsB[sel];
        __half* Ks = KsB[sel];
#pragma unroll
        for (int it = 0; it < 2; it++) {
            const int idx = tid + it * 256;
            const int r = idx >> 3, c8 = (idx & 7) * 8;
            const size_t off = (size_t)(b * T_SZ + i0 + r) * DIM + d0 + c8;
            cpasync16(sptr(&Qs[r * KP + c8]), g_q + off);
        }
#pragma unroll
        for (int it = 0; it < 6; it++) {
            const int idx = tid + it * 256;
            const int r = idx >> 3, c8 = (idx & 7) * 8;
            const int j = jbase + r;
            const int jc = j < 0 ? 0 : j;
            const size_t off = (size_t)(b * T_SZ + jc) * DIM + d0 + c8;
            cpasync16(sptr(&Ks[r * KP + c8]), g_k + off);
        }
        asm volatile("cp.async.commit_group;");
    };

    load_qk(0, 0);

    for (int dc = 0; dc < DIM / DC; dc++) {
        const int cur = dc & 1;
        if (dc + 1 < DIM / DC) {
            __syncthreads();                 // done reading buf[cur^1]
            load_qk(dc + 1, cur ^ 1);
            asm volatile("cp.async.wait_group 1;");
        } else {
            asm volatile("cp.async.wait_group 0;");
        }
        __syncthreads();

        __half* Qs = QsB[cur];
        __half* Ks = KsB[cur];
#pragma unroll
        for (int ks = 0; ks < DC / 16; ks++) {
            const int k = ks * 16;
            uint32_t a[2][4];
#pragma unroll
            for (int mi = 0; mi < 2; mi++)
                ldsm4(a[mi], sptr(&Qs[(wm + mi * 16 + arow) * KP + k + acol]));
#pragma unroll
            for (int np = 0; np < 3; np++) {
                uint32_t bb[4];
                ldsm4(bb, sptr(&Ks[(wn + np * 16 + brow) * KP + k + bcol]));
#pragma unroll
                for (int mi = 0; mi < 2; mi++) {
                    mma16816(acc[mi][2 * np],     a[mi], bb[0], bb[1]);
                    mma16816(acc[mi][2 * np + 1], a[mi], bb[2], bb[3]);
                }
            }
        }
    }
    __syncthreads();

    // masked store of S to Ps
#pragma unroll
    for (int mi = 0; mi < 2; mi++) {
#pragma unroll
        for (int ni = 0; ni < 6; ni++) {
            const int m0 = wm + mi * 16 + g;
            const int n0 = wn + ni * 8 + tig * 2;
#pragma unroll
            for (int e = 0; e < 4; e++) {
                const int m = m0 + (e >> 1) * 8;
                const int n = n0 + (e & 1);
                const bool valid = (n >= m) && (n <= m + HIST) && (jbase + n >= 0);
                Ps[m * PP + n] = valid ? acc[mi][ni][e] : -1e30f;
            }
        }
    }
    __syncthreads();

    // ---------------- phase B: softmax + fp16 P ------------------------------
#pragma unroll
    for (int rr = 0; rr < 8; rr++) {
        const int q = warp * 8 + rr;
        float v[6];
        float mx = -1e30f;
#pragma unroll
        for (int s = 0; s < 6; s++) {
            v[s] = Ps[q * PP + lane + 32 * s];
            mx = fmaxf(mx, v[s]);
        }
#pragma unroll
        for (int off = 16; off; off >>= 1)
            mx = fmaxf(mx, __shfl_xor_sync(0xFFFFFFFFu, mx, off));
        float sum = 0.f;
#pragma unroll
        for (int s = 0; s < 6; s++) {
            v[s] = __expf(v[s] - mx);
            sum += v[s];
        }
#pragma unroll
        for (int off = 16; off; off >>= 1)
            sum += __shfl_xor_sync(0xFFFFFFFFu, sum, off);
        const float inv = 1.f / sum;
#pragma unroll
        for (int s = 0; s < 6; s++)
            Pw[q * PP + lane + 32 * s] = __float2half_rn(v[s] * inv);
    }
    __syncthreads();   // Ps reads done before Vt loads overwrite region

    // ---------------- phase C: O = P V (pipelined over dc) -------------------
    const int wn2 = (warp & 3) * 16;       // 4 warp-groups along D (64)
    const size_t vbase = (size_t)b * DIM * T_SZ;

    auto load_v = [&](int dc, int sel) {
        const int d0 = dc * DC;
        __half* Vt = VtB[sel];
#pragma unroll
        for (int it = 0; it < 6; it++) {
            const int idx = tid + it * 256;
            const int r = idx / 24;            // d-row 0..63
            const int c8 = (idx % 24) * 8;     // key col 0..184
            int j = jbase + c8;
            if (j < 0) j = 0;
            const size_t off = vbase + (size_t)(d0 + r) * T_SZ + j;
            cpasync16(sptr(&Vt[r * PP + c8]), g_vt + off);
        }
        asm volatile("cp.async.commit_group;");
    };

    load_v(0, 0);

    for (int dc = 0; dc < DIM / DC; dc++) {
        const int cur = dc & 1;
        if (dc + 1 < DIM / DC) {
            __syncthreads();
            load_v(dc + 1, cur ^ 1);
            asm volatile("cp.async.wait_group 1;");
        } else {
            asm volatile("cp.async.wait_group 0;");
        }
        __syncthreads();

        __half* Vt = VtB[cur];
        const int d0 = dc * DC;

        float oacc[2][2][4] = {};
#pragma unroll
        for (int ks = 0; ks < NK / 16; ks++) {
            const int k = ks * 16;
            uint32_t p[2][4];
#pragma unroll
            for (int mi = 0; mi < 2; mi++)
                ldsm4(p[mi], sptr(&Pw[(wm + mi * 16 + arow) * PP + k + acol]));
            uint32_t vv[4];
            ldsm4(vv, sptr(&Vt[(wn2 + brow) * PP + k + bcol]));
#pragma unroll
            for (int mi = 0; mi < 2; mi++) {
                mma16816(oacc[mi][0], p[mi], vv[0], vv[1]);
                mma16816(oacc[mi][1], p[mi], vv[2], vv[3]);
            }
        }

#pragma unroll
        for (int mi = 0; mi < 2; mi++) {
#pragma unroll
            for (int ni = 0; ni < 2; ni++) {
                const int m0 = wm + mi * 16 + g;
                const int col = d0 + wn2 + ni * 8 + tig * 2;
                const size_t row = (size_t)b * T_SZ + i0 + m0;
                float2 v0 = {oacc[mi][ni][0], oacc[mi][ni][1]};
                float2 v1 = {oacc[mi][ni][2], oacc[mi][ni][3]};
                *(float2*)&out[row * DIM + col]       = v0;
                *(float2*)&out[(row + 8) * DIM + col] = v1;
            }
        }
    }
}

// ---------------- launch -----------------------------------------------------
extern "C" void kernel_launch(void* const* d_in, const int* in_sizes, int n_in,
                              void* d_out, int out_size)
{
    const float* x    = (const float*)d_in[0];
    const float* Wqkv = (const float*)d_in[1];
    const float* bqkv = (const float*)d_in[2];
    float* out = (float*)d_out;

    cudaFuncSetAttribute(attn_mma,
                         cudaFuncAttributeMaxDynamicSharedMemorySize, AT_SMEM);
    cudaFuncSetAttribute(qkv_mma,
                         cudaFuncAttributeMaxDynamicSharedMemorySize, GSMEM_BYTES);

    __half *pa, *pw;
    cudaGetSymbolAddress((void**)&pa, g_A);
    cudaGetSymbolAddress((void**)&pw, g_W);

    {
        int n4 = NX4 + NW4;
        cvt16_both<<<(n4 + 255) / 256, 256>>>(x, Wqkv, pa, pw);
    }

    dim3 ggrid(E3 / GBN, M_TOT / GBM);       // (12, 128)
    qkv_mma<<<ggrid, GTHREADS, GSMEM_BYTES>>>(bqkv);

    dim3 agrid(T_SZ / QT, B_SZ);             // (64, 4)
    attn_mma<<<agrid, 256, AT_SMEM>>>(out);
}